// round 14
// baseline (speedup 1.0000x reference)
#include <cuda_runtime.h>
#include <cuda_fp16.h>

#define BATCH 128
#define SEQ   256
#define UNITS 128
#define NV    512          // 4*UNITS gate width
#define DEPTH 655
#define KROWS 2620         // 4*DEPTH
#define NT    256          // threads per lstm block
#define RROWS 64           // Wh rows register-resident fp32 per column
#define FROWS (UNITS - RROWS)   // 64 rows register-resident fp16 per column
#define RGRP4 (RROWS / 4)       // 16 fp32 4-row groups
#define FGRP4 (FROWS / 4)       // 16 fp16 4-row groups

// Precomputed M = W_dense @ Wx with PERMUTED columns:
//   perm(c) = 2*c           for c in [0,256)
//   perm(c) = 2*(c-256)+1   for c in [256,512)
// so the two gate columns (c, c+256) owned by one thread sit adjacent,
// making every gather a single float2 (LDG.64). Row KROWS holds
// b_dense@Wx + b_lstm under the same permutation.
__device__ float g_M[(KROWS + 1) * NV];

typedef unsigned long long ull;

#define FMA2(acc, a, b) \
    asm("fma.rn.f32x2 %0, %1, %2, %0;" : "+l"(acc) : "l"(a), "l"(b))

__device__ __forceinline__ ull pk(float lo, float hi) {
    return (ull)__float_as_uint(lo) | ((ull)__float_as_uint(hi) << 32);
}
__device__ __forceinline__ float red2(ull a, ull b) {
    ull s;
    asm("add.rn.f32x2 %0, %1, %2;" : "=l"(s) : "l"(a), "l"(b));
    return __uint_as_float((unsigned)s) + __uint_as_float((unsigned)(s >> 32));
}
__device__ __forceinline__ float sigmoid_f(float x) {
    return __fdividef(1.f, 1.f + __expf(-x));
}
__device__ __forceinline__ float tanh_f(float x) {
    return 1.f - __fdividef(2.f, __expf(2.f * x) + 1.f);
}
// fp16 pair (packed in u32) -> packed f32x2 operand
__device__ __forceinline__ ull h2f2(unsigned u) {
    float2 f = __half22float2(*reinterpret_cast<const __half2*>(&u));
    return pk(f.x, f.y);
}
__device__ __forceinline__ unsigned f2h2(float a, float b) {
    __half2 h = __floats2half2_rn(a, b);
    return *reinterpret_cast<unsigned*>(&h);
}
__device__ __forceinline__ int permc(int c) {
    return (c < 256) ? 2 * c : 2 * (c - 256) + 1;
}

// ---------------------------------------------------------------------------
// M = W_dense @ Wx (permuted columns). Block 0 additionally computes the bias
// row KROWS = b_dense@Wx + b_lstm (prep_bb folded in: one fewer launch).
// ---------------------------------------------------------------------------
#define RPB 20
__global__ __launch_bounds__(512) void prep_M_kernel(const float* __restrict__ Wd,
                                                     const float* __restrict__ Wx,
                                                     const float* __restrict__ b_dense,
                                                     const float* __restrict__ b_lstm) {
    __shared__ float wd[RPB * UNITS];
    const int t = threadIdx.x;
    const int r0 = blockIdx.x * RPB;
    for (int idx = t; idx < RPB * UNITS; idx += 512)
        wd[idx] = Wd[r0 * UNITS + idx];
    __syncthreads();

    float acc[RPB];
#pragma unroll
    for (int r = 0; r < RPB; ++r) acc[r] = 0.f;
    float accb = 0.f;
    const bool do_bb = (blockIdx.x == 0);

    for (int u = 0; u < UNITS; u += 4) {
        float x0 = Wx[(u + 0) * NV + t];
        float x1 = Wx[(u + 1) * NV + t];
        float x2 = Wx[(u + 2) * NV + t];
        float x3 = Wx[(u + 3) * NV + t];
#pragma unroll
        for (int r = 0; r < RPB; ++r) {
            float4 w = *(const float4*)&wd[r * UNITS + u];
            acc[r] = fmaf(w.x, x0, fmaf(w.y, x1, fmaf(w.z, x2, fmaf(w.w, x3, acc[r]))));
        }
        if (do_bb) {
            accb = fmaf(b_dense[u],     x0, accb);
            accb = fmaf(b_dense[u + 1], x1, accb);
            accb = fmaf(b_dense[u + 2], x2, accb);
            accb = fmaf(b_dense[u + 3], x3, accb);
        }
    }
    const int pc = permc(t);
#pragma unroll
    for (int r = 0; r < RPB; ++r)
        g_M[(r0 + r) * NV + pc] = acc[r];
    if (do_bb)
        g_M[KROWS * NV + pc] = accb + b_lstm[t];
}

// ---------------------------------------------------------------------------
__global__ void ctx_kernel(const int* __restrict__ last_rule,
                           const int* __restrict__ move_count,
                           const int* __restrict__ node_count,
                           const int* __restrict__ problem_type,
                           float* __restrict__ out, int out_size) {
    const int b = blockIdx.x, j = threadIdx.x;
    if (j < 35) {
        float v;
        if (j == 0)      v = (float)last_rule[b];
        else if (j == 1) v = (float)move_count[b];
        else if (j == 2) v = (float)node_count[b];
        else             v = (problem_type[b] == (j - 3)) ? 1.f : 0.f;
        out[b * 35 + j] = v;
    }
    const int seq_off = BATCH * 35 + BATCH * UNITS + BATCH * SEQ * UNITS;
    if (b == 0 && j == 63 && out_size > seq_off)
        out[seq_off] = (float)SEQ;
}

// ---------------------------------------------------------------------------
// LSTM: one block per batch row; 256 threads. Warp w covers elements
// [16w,16w+16). Lane l<16 owns element e=16w+l with gate cols (e, e+256)
// = (i, g); lane l+16 owns (e+128, e+384) = (f, o). Two shfl.xor(16) deliver
// f,o to the (i,g) lane; c,h in registers; h via ping-pong smem; ONE
// __syncthreads per step.
// ALL Wh weights register-resident: rows [0,64) fp32 f32x2 pairs, rows
// [64,128) fp16-packed u32 pairs (converted per use on the idle ALU pipe).
// ZERO weight shared-memory traffic. g_M gathers are LDG.64 (both columns).
// ---------------------------------------------------------------------------
#define SMEM_LSTM (2 * UNITS * 4 + 4 * SEQ * 4)

__global__ __launch_bounds__(NT, 1) void lstm_kernel(
    const int* __restrict__ bwd, const int* __restrict__ fwd,
    const int* __restrict__ lbwd, const int* __restrict__ lfwd,
    const float* __restrict__ Wh,
    float* __restrict__ out_h,    // [B][S][UNITS]
    float* __restrict__ out_lv) { // [B][UNITS]
    extern __shared__ unsigned char smraw[];
    float* h0  = (float*)smraw;
    float* h1  = h0 + UNITS;
    int*   idx_s = (int*)(h1 + UNITS);

    const int b = blockIdx.x;
    const int t = threadIdx.x;
    const int l = t & 31;
    const int role = l >> 4;                 // 0: (i,g) owner, 1: (f,o) owner
    const int e  = (t >> 5) * 16 + (l & 15); // element in [0,128)
    const int cA = e + role * 128;           // i (role0) / f (role1)  [0,256)
    const int cB = cA + 256;                 // g (role0) / o (role1)
    const int pc = 2 * cA;                   // permuted base: (cA,cB) adjacent

    // ---- weights: rows [0,RROWS) -> fp32 register pairs per column ----
    ull wA[RROWS / 2], wB[RROWS / 2];
#pragma unroll
    for (int p = 0; p < RROWS / 2; ++p) {
        int i = 2 * p;
        wA[p] = pk(Wh[i * NV + cA], Wh[(i + 1) * NV + cA]);
        wB[p] = pk(Wh[i * NV + cB], Wh[(i + 1) * NV + cB]);
    }
    // rows [RROWS,128) -> fp16 register pairs per column
    unsigned fA[FROWS / 2], fB[FROWS / 2];
#pragma unroll
    for (int p = 0; p < FROWS / 2; ++p) {
        int i = RROWS + 2 * p;
        fA[p] = f2h2(Wh[i * NV + cA], Wh[(i + 1) * NV + cA]);
        fB[p] = f2h2(Wh[i * NV + cB], Wh[(i + 1) * NV + cB]);
    }

    // ---- stage gather indices with offsets pre-added (t covers SEQ=256) ----
    idx_s[t]           = bwd[b * SEQ + t];
    idx_s[SEQ + t]     = DEPTH     + fwd[b * SEQ + t];
    idx_s[2 * SEQ + t] = 2 * DEPTH + lbwd[b * SEQ + t];
    idx_s[3 * SEQ + t] = 3 * DEPTH + lfwd[b * SEQ + t];
    if (t < UNITS) h0[t] = 0.f;
    float c_r = 0.f, h_last = 0.f;
    const float2 bb = *(const float2*)&g_M[KROWS * NV + pc];
    __syncthreads();

    // xz for s = 0 (both columns via one float2 per index)
    float2 i0 = *(const float2*)&g_M[idx_s[0] * NV + pc];
    float2 i1 = *(const float2*)&g_M[idx_s[SEQ] * NV + pc];
    float2 i2 = *(const float2*)&g_M[idx_s[2 * SEQ] * NV + pc];
    float2 i3 = *(const float2*)&g_M[idx_s[3 * SEQ] * NV + pc];
    float xzA = i0.x + i1.x + i2.x + i3.x + bb.x;
    float xzB = i0.y + i1.y + i2.y + i3.y + bb.y;

    for (int s = 0; s < SEQ; ++s) {
        // prefetch next step's xz components (L2-resident, float2 = both cols)
        const int sn = (s + 1 < SEQ) ? s + 1 : s;
        float2 m0 = *(const float2*)&g_M[idx_s[sn] * NV + pc];
        float2 m1 = *(const float2*)&g_M[idx_s[SEQ + sn] * NV + pc];
        float2 m2 = *(const float2*)&g_M[idx_s[2 * SEQ + sn] * NV + pc];
        float2 m3 = *(const float2*)&g_M[idx_s[3 * SEQ + sn] * NV + pc];

        // z = xz + h . Wh[:,c]  for cA and cB (4 independent f32x2 chains)
        const ulonglong2* hp = (const ulonglong2*)((s & 1) ? h1 : h0);
        ull aA0 = pk(xzA, 0.f), aA1 = 0ull;
        ull aB0 = pk(xzB, 0.f), aB1 = 0ull;
#pragma unroll
        for (int g = 0; g < RGRP4; ++g) {       // 16 groups x 4 rows = 64 fp32
            ulonglong2 hv = hp[g];              // broadcast LDS.128
            FMA2(aA0, hv.x, wA[2 * g]);
            FMA2(aA1, hv.y, wA[2 * g + 1]);
            FMA2(aB0, hv.x, wB[2 * g]);
            FMA2(aB1, hv.y, wB[2 * g + 1]);
        }
#pragma unroll
        for (int g = 0; g < FGRP4; ++g) {       // 16 groups x 4 rows = 64 fp16
            ulonglong2 hv = hp[RGRP4 + g];      // broadcast LDS.128
            FMA2(aA0, hv.x, h2f2(fA[2 * g]));
            FMA2(aA1, hv.y, h2f2(fA[2 * g + 1]));
            FMA2(aB0, hv.x, h2f2(fB[2 * g]));
            FMA2(aB1, hv.y, h2f2(fB[2 * g + 1]));
        }
        float zA = red2(aA0, aA1);
        float zB = red2(aB0, aB1);

        // activations: cA is i or f -> sigmoid; cB is g (tanh) or o (sigmoid)
        float actA = sigmoid_f(zA);
        float actB = role ? sigmoid_f(zB) : tanh_f(zB);

        // exchange: (i,g) lane receives (f,o) from lane+16
        float xf = __shfl_xor_sync(0xffffffffu, actA, 16);
        float xo = __shfl_xor_sync(0xffffffffu, actB, 16);

        float* hw = (s & 1) ? h0 : h1;
        if (role == 0) {
            float cn = fmaf(xf, c_r, actA * actB);   // f*c + i*g
            c_r = cn;
            float hn = xo * tanh_f(cn);
            hw[e] = hn;
            out_h[(b * SEQ + s) * UNITS + e] = hn;
            h_last = hn;
        }
        xzA = m0.x + m1.x + m2.x + m3.x + bb.x;
        xzB = m0.y + m1.y + m2.y + m3.y + bb.y;
        __syncthreads();
    }
    if (role == 0) out_lv[b * UNITS + e] = h_last;
}

// ---------------------------------------------------------------------------
extern "C" void kernel_launch(void* const* d_in, const int* in_sizes, int n_in,
                              void* d_out, int out_size) {
    const int*   move_count   = (const int*)d_in[0];
    // d_in[1] = moves_remaining (unused by reference)
    const int*   last_rule    = (const int*)d_in[2];
    const int*   node_count   = (const int*)d_in[3];
    const int*   problem_type = (const int*)d_in[4];
    const int*   bwd          = (const int*)d_in[5];
    const int*   fwd          = (const int*)d_in[6];
    const int*   lbwd         = (const int*)d_in[7];
    const int*   lfwd         = (const int*)d_in[8];
    const float* Wd           = (const float*)d_in[9];
    const float* b_dense      = (const float*)d_in[10];
    const float* Wx           = (const float*)d_in[11];
    const float* Wh           = (const float*)d_in[12];
    const float* b_lstm       = (const float*)d_in[13];
    float* out = (float*)d_out;

    prep_M_kernel<<<KROWS / RPB, 512>>>(Wd, Wx, b_dense, b_lstm);
    ctx_kernel<<<BATCH, 64>>>(last_rule, move_count, node_count, problem_type, out, out_size);

    const int off_lv = BATCH * 35;                 // 4480
    const int off_h  = off_lv + BATCH * UNITS;     // 20864
    lstm_kernel<<<BATCH, NT, SMEM_LSTM>>>(bwd, fwd, lbwd, lfwd, Wh,
                                          out + off_h, out + off_lv);
}

// round 15
// speedup vs baseline: 2.2848x; 2.2848x over previous
#include <cuda_runtime.h>
#include <cuda_fp16.h>

#define BATCH 128
#define SEQ   256
#define UNITS 128
#define NV    512          // 4*UNITS gate width
#define DEPTH 655
#define KROWS 2620         // 4*DEPTH
#define NT    256          // threads per lstm block
#define RROWS 96           // Wh rows register-resident fp32 per column
#define SROWS (UNITS - RROWS)   // 32 rows in smem (fp16)
#define RPAIR (RROWS / 2)       // 48 fp32 row-pairs per column
#define RGRP4 (RROWS / 4)       // 24 fp32 4-row groups
#define SGRP8 (SROWS / 8)       // 4 fp16 smem groups of 8 rows

// Precomputed M = W_dense @ Wx with PERMUTED columns:
//   perm(c) = 2*c           for c in [0,256)
//   perm(c) = 2*(c-256)+1   for c in [256,512)
// so the two gate columns (c, c+256) owned by one thread sit adjacent,
// making every gather a single float2 (LDG.64). Row KROWS holds
// b_dense@Wx + b_lstm under the same permutation.
__device__ float g_M[(KROWS + 1) * NV];

typedef unsigned long long ull;

#define FMA2(acc, a, b) \
    asm("fma.rn.f32x2 %0, %1, %2, %0;" : "+l"(acc) : "l"(a), "l"(b))

__device__ __forceinline__ ull pk(float lo, float hi) {
    return (ull)__float_as_uint(lo) | ((ull)__float_as_uint(hi) << 32);
}
__device__ __forceinline__ float red2(ull a, ull b) {
    ull s;
    asm("add.rn.f32x2 %0, %1, %2;" : "=l"(s) : "l"(a), "l"(b));
    return __uint_as_float((unsigned)s) + __uint_as_float((unsigned)(s >> 32));
}
__device__ __forceinline__ float sigmoid_f(float x) {
    return __fdividef(1.f, 1.f + __expf(-x));
}
__device__ __forceinline__ float tanh_f(float x) {
    return 1.f - __fdividef(2.f, __expf(2.f * x) + 1.f);
}
// fp16 pair (packed in u32) -> packed f32x2 operand
__device__ __forceinline__ ull h2f2(unsigned u) {
    float2 f = __half22float2(*reinterpret_cast<const __half2*>(&u));
    return pk(f.x, f.y);
}
__device__ __forceinline__ unsigned f2h2(float a, float b) {
    __half2 h = __floats2half2_rn(a, b);
    return *reinterpret_cast<unsigned*>(&h);
}
__device__ __forceinline__ int permc(int c) {
    return (c < 256) ? 2 * c : 2 * (c - 256) + 1;
}

// ---------------------------------------------------------------------------
// M = W_dense @ Wx (permuted columns). RPB=10 -> 262 blocks = 2 blocks/SM
// (32 warps/SM) for latency hiding. Block 0 also computes the bias row
// KROWS = b_dense@Wx + b_lstm.
// ---------------------------------------------------------------------------
#define RPB 10
__global__ __launch_bounds__(512) void prep_M_kernel(const float* __restrict__ Wd,
                                                     const float* __restrict__ Wx,
                                                     const float* __restrict__ b_dense,
                                                     const float* __restrict__ b_lstm) {
    __shared__ float wd[RPB * UNITS];
    const int t = threadIdx.x;
    const int r0 = blockIdx.x * RPB;
    for (int idx = t; idx < RPB * UNITS; idx += 512)
        wd[idx] = Wd[r0 * UNITS + idx];
    __syncthreads();

    float acc[RPB];
#pragma unroll
    for (int r = 0; r < RPB; ++r) acc[r] = 0.f;
    float accb = 0.f;
    const bool do_bb = (blockIdx.x == 0);

    for (int u = 0; u < UNITS; u += 4) {
        float x0 = Wx[(u + 0) * NV + t];
        float x1 = Wx[(u + 1) * NV + t];
        float x2 = Wx[(u + 2) * NV + t];
        float x3 = Wx[(u + 3) * NV + t];
#pragma unroll
        for (int r = 0; r < RPB; ++r) {
            float4 w = *(const float4*)&wd[r * UNITS + u];
            acc[r] = fmaf(w.x, x0, fmaf(w.y, x1, fmaf(w.z, x2, fmaf(w.w, x3, acc[r]))));
        }
        if (do_bb) {
            accb = fmaf(b_dense[u],     x0, accb);
            accb = fmaf(b_dense[u + 1], x1, accb);
            accb = fmaf(b_dense[u + 2], x2, accb);
            accb = fmaf(b_dense[u + 3], x3, accb);
        }
    }
    const int pc = permc(t);
#pragma unroll
    for (int r = 0; r < RPB; ++r)
        g_M[(r0 + r) * NV + pc] = acc[r];
    if (do_bb)
        g_M[KROWS * NV + pc] = accb + b_lstm[t];
}

// ---------------------------------------------------------------------------
__global__ void ctx_kernel(const int* __restrict__ last_rule,
                           const int* __restrict__ move_count,
                           const int* __restrict__ node_count,
                           const int* __restrict__ problem_type,
                           float* __restrict__ out, int out_size) {
    const int b = blockIdx.x, j = threadIdx.x;
    if (j < 35) {
        float v;
        if (j == 0)      v = (float)last_rule[b];
        else if (j == 1) v = (float)move_count[b];
        else if (j == 2) v = (float)node_count[b];
        else             v = (problem_type[b] == (j - 3)) ? 1.f : 0.f;
        out[b * 35 + j] = v;
    }
    const int seq_off = BATCH * 35 + BATCH * UNITS + BATCH * SEQ * UNITS;
    if (b == 0 && j == 63 && out_size > seq_off)
        out[seq_off] = (float)SEQ;
}

// ---------------------------------------------------------------------------
// LSTM (R9 structure, frozen register layout): one block per batch row;
// 256 threads. Warp w covers elements [16w,16w+16). Lane l<16 owns element
// e=16w+l with gate cols (e, e+256)=(i,g); lane l+16 owns (e+128, e+384)
// =(f,o). Two shfl.xor(16) deliver f,o to the (i,g) lane; c,h in registers;
// h via ping-pong smem -> ONE __syncthreads per step.
// Wh rows [0,96) fp32 in registers; rows [96,128) fp16 in smem (uint4 = 8
// rows per column per LDS.128). g_M gathers are LDG.64 (both columns);
// staged indices are pre-multiplied by NV (saves per-step IMADs).
// ---------------------------------------------------------------------------
#define WH_HALF (SGRP8 * NT * 16)      // 16 KB per column-set (fp16)
#define SMEM_LSTM (2 * WH_HALF + 2 * UNITS * 4 + 4 * SEQ * 4)

__global__ __launch_bounds__(NT, 1) void lstm_kernel(
    const int* __restrict__ bwd, const int* __restrict__ fwd,
    const int* __restrict__ lbwd, const int* __restrict__ lfwd,
    const float* __restrict__ Wh,
    float* __restrict__ out_h,    // [B][S][UNITS]
    float* __restrict__ out_lv) { // [B][UNITS]
    extern __shared__ unsigned char smraw[];
    uint4* whA = (uint4*)smraw;
    uint4* whB = (uint4*)(smraw + WH_HALF);
    float* h0  = (float*)(smraw + 2 * WH_HALF);
    float* h1  = h0 + UNITS;
    int*   idx_s = (int*)(h1 + UNITS);

    const int b = blockIdx.x;
    const int t = threadIdx.x;
    const int l = t & 31;
    const int role = l >> 4;                 // 0: (i,g) owner, 1: (f,o) owner
    const int e  = (t >> 5) * 16 + (l & 15); // element in [0,128)
    const int cA = e + role * 128;           // i (role0) / f (role1)  [0,256)
    const int cB = cA + 256;                 // g (role0) / o (role1)
    const int pc = 2 * cA;                   // permuted base: (cA,cB) adjacent

    // ---- weights: rows [0,RROWS) -> fp32 register pairs per column ----
    ull wA[RPAIR], wB[RPAIR];
#pragma unroll
    for (int p = 0; p < RPAIR; ++p) {
        int i = 2 * p;
        wA[p] = pk(Wh[i * NV + cA], Wh[(i + 1) * NV + cA]);
        wB[p] = pk(Wh[i * NV + cB], Wh[(i + 1) * NV + cB]);
    }
    // rows [RROWS,128) -> smem fp16, 8 rows per uint4 per column
#pragma unroll
    for (int g = 0; g < SGRP8; ++g) {
        int i = RROWS + 8 * g;
        uint4 vA, vB;
        vA.x = f2h2(Wh[(i + 0) * NV + cA], Wh[(i + 1) * NV + cA]);
        vA.y = f2h2(Wh[(i + 2) * NV + cA], Wh[(i + 3) * NV + cA]);
        vA.z = f2h2(Wh[(i + 4) * NV + cA], Wh[(i + 5) * NV + cA]);
        vA.w = f2h2(Wh[(i + 6) * NV + cA], Wh[(i + 7) * NV + cA]);
        vB.x = f2h2(Wh[(i + 0) * NV + cB], Wh[(i + 1) * NV + cB]);
        vB.y = f2h2(Wh[(i + 2) * NV + cB], Wh[(i + 3) * NV + cB]);
        vB.z = f2h2(Wh[(i + 4) * NV + cB], Wh[(i + 5) * NV + cB]);
        vB.w = f2h2(Wh[(i + 6) * NV + cB], Wh[(i + 7) * NV + cB]);
        whA[g * NT + t] = vA;
        whB[g * NT + t] = vB;
    }

    // ---- stage gather indices, pre-multiplied by NV, offsets pre-added ----
    idx_s[t]           = bwd[b * SEQ + t] * NV;
    idx_s[SEQ + t]     = (DEPTH     + fwd[b * SEQ + t]) * NV;
    idx_s[2 * SEQ + t] = (2 * DEPTH + lbwd[b * SEQ + t]) * NV;
    idx_s[3 * SEQ + t] = (3 * DEPTH + lfwd[b * SEQ + t]) * NV;
    if (t < UNITS) h0[t] = 0.f;
    float c_r = 0.f, h_last = 0.f;
    const float2 bb = *(const float2*)&g_M[KROWS * NV + pc];
    __syncthreads();

    // xz for s = 0 (both columns via one float2 per index)
    float2 i0 = *(const float2*)&g_M[idx_s[0] + pc];
    float2 i1 = *(const float2*)&g_M[idx_s[SEQ] + pc];
    float2 i2 = *(const float2*)&g_M[idx_s[2 * SEQ] + pc];
    float2 i3 = *(const float2*)&g_M[idx_s[3 * SEQ] + pc];
    float xzA = i0.x + i1.x + i2.x + i3.x + bb.x;
    float xzB = i0.y + i1.y + i2.y + i3.y + bb.y;

    for (int s = 0; s < SEQ; ++s) {
        // prefetch next step's xz components (L2-resident, float2 = both cols)
        const int sn = (s + 1 < SEQ) ? s + 1 : s;
        float2 m0 = *(const float2*)&g_M[idx_s[sn] + pc];
        float2 m1 = *(const float2*)&g_M[idx_s[SEQ + sn] + pc];
        float2 m2 = *(const float2*)&g_M[idx_s[2 * SEQ + sn] + pc];
        float2 m3 = *(const float2*)&g_M[idx_s[3 * SEQ + sn] + pc];

        // z = xz + h . Wh[:,c]  for cA and cB (4 independent f32x2 chains)
        const ulonglong2* hp = (const ulonglong2*)((s & 1) ? h1 : h0);
        ull aA0 = pk(xzA, 0.f), aA1 = 0ull;
        ull aB0 = pk(xzB, 0.f), aB1 = 0ull;
#pragma unroll
        for (int g = 0; g < RGRP4; ++g) {       // 24 groups x 4 rows = 96 rows
            ulonglong2 hv = hp[g];              // broadcast LDS.128
            FMA2(aA0, hv.x, wA[2 * g]);
            FMA2(aA1, hv.y, wA[2 * g + 1]);
            FMA2(aB0, hv.x, wB[2 * g]);
            FMA2(aB1, hv.y, wB[2 * g + 1]);
        }
#pragma unroll
        for (int g = 0; g < SGRP8; ++g) {       // 4 groups x 8 rows = 32 rows
            ulonglong2 hv0 = hp[RGRP4 + 2 * g];     // broadcast LDS.128
            ulonglong2 hv1 = hp[RGRP4 + 2 * g + 1]; // broadcast LDS.128
            uint4 a4 = whA[g * NT + t];             // 8 fp16 weights, col cA
            uint4 b4 = whB[g * NT + t];             // 8 fp16 weights, col cB
            FMA2(aA0, hv0.x, h2f2(a4.x));
            FMA2(aA1, hv0.y, h2f2(a4.y));
            FMA2(aA0, hv1.x, h2f2(a4.z));
            FMA2(aA1, hv1.y, h2f2(a4.w));
            FMA2(aB0, hv0.x, h2f2(b4.x));
            FMA2(aB1, hv0.y, h2f2(b4.y));
            FMA2(aB0, hv1.x, h2f2(b4.z));
            FMA2(aB1, hv1.y, h2f2(b4.w));
        }
        float zA = red2(aA0, aA1);
        float zB = red2(aB0, aB1);

        // activations: cA is i or f -> sigmoid; cB is g (tanh) or o (sigmoid)
        float actA = sigmoid_f(zA);
        float actB = role ? sigmoid_f(zB) : tanh_f(zB);

        // exchange: (i,g) lane receives (f,o) from lane+16
        float xf = __shfl_xor_sync(0xffffffffu, actA, 16);
        float xo = __shfl_xor_sync(0xffffffffu, actB, 16);

        float* hw = (s & 1) ? h0 : h1;
        if (role == 0) {
            float cn = fmaf(xf, c_r, actA * actB);   // f*c + i*g
            c_r = cn;
            float hn = xo * tanh_f(cn);
            hw[e] = hn;
            out_h[(b * SEQ + s) * UNITS + e] = hn;
            h_last = hn;
        }
        xzA = m0.x + m1.x + m2.x + m3.x + bb.x;
        xzB = m0.y + m1.y + m2.y + m3.y + bb.y;
        __syncthreads();
    }
    if (role == 0) out_lv[b * UNITS + e] = h_last;
}

// ---------------------------------------------------------------------------
extern "C" void kernel_launch(void* const* d_in, const int* in_sizes, int n_in,
                              void* d_out, int out_size) {
    const int*   move_count   = (const int*)d_in[0];
    // d_in[1] = moves_remaining (unused by reference)
    const int*   last_rule    = (const int*)d_in[2];
    const int*   node_count   = (const int*)d_in[3];
    const int*   problem_type = (const int*)d_in[4];
    const int*   bwd          = (const int*)d_in[5];
    const int*   fwd          = (const int*)d_in[6];
    const int*   lbwd         = (const int*)d_in[7];
    const int*   lfwd         = (const int*)d_in[8];
    const float* Wd           = (const float*)d_in[9];
    const float* b_dense      = (const float*)d_in[10];
    const float* Wx           = (const float*)d_in[11];
    const float* Wh           = (const float*)d_in[12];
    const float* b_lstm       = (const float*)d_in[13];
    float* out = (float*)d_out;

    cudaFuncSetAttribute(lstm_kernel, cudaFuncAttributeMaxDynamicSharedMemorySize,
                         SMEM_LSTM);

    prep_M_kernel<<<KROWS / RPB, 512>>>(Wd, Wx, b_dense, b_lstm);
    ctx_kernel<<<BATCH, 64>>>(last_rule, move_count, node_count, problem_type, out, out_size);

    const int off_lv = BATCH * 35;                 // 4480
    const int off_h  = off_lv + BATCH * UNITS;     // 20864
    lstm_kernel<<<BATCH, NT, SMEM_LSTM>>>(bwd, fwd, lbwd, lfwd, Wh,
                                          out + off_h, out + off_lv);
}